// round 7
// baseline (speedup 1.0000x reference)
#include <cuda_runtime.h>

// A [B=256, d=512, d=512] fp32, mask [16, 512] fp32, regimes [B] int32.
// Output: 1 float scalar.
#define D 512
#define D4 (D / 4)          // 128 float4 groups per row
#define ROWS_PER_BLK 128    // 4 row-chunks per batch -> 1024 blocks = ONE wave
#define NBLK 1024           // (512/128) * 256
#define MAX_REG 64
#define MAX_B 4096

__device__ float    g_part[NBLK];
__device__ unsigned g_cnt;            // zero-init; reset to 0 by the last block

__global__ void __launch_bounds__(256)
k_reduce(const float* __restrict__ A,
         const float* __restrict__ mask,
         const int* __restrict__ regimes,
         int B, int n_regimes, float* __restrict__ out) {
    const int tid  = threadIdx.x;
    const int wid  = tid >> 5;
    const int lane = tid & 31;
    const int b    = blockIdx.y;

    const int e = regimes[b];
    const bool valid = (e < n_regimes);
    const int ec = e < 0 ? 0 : (e >= n_regimes ? n_regimes - 1 : e);

    __shared__ float4 smask[D4];
    if (tid < D4) {
        float4 m = reinterpret_cast<const float4*>(mask + (long long)ec * D)[tid];
        if (!valid) m = make_float4(0.f, 0.f, 0.f, 0.f);
        smask[tid] = m;
    }
    __syncthreads();

    const int j4   = tid & (D4 - 1);   // column group
    const int rsub = tid >> 7;         // 0/1 row interleave
    const float4 m = smask[j4];

    // Dense streaming read: uniform work per block, batched loads for MLP.
    const float4* base = reinterpret_cast<const float4*>(
        A + ((long long)b * D + (long long)blockIdx.x * ROWS_PER_BLK + rsub) * D) + j4;

    float acc = 0.f;
    #pragma unroll 4
    for (int i = 0; i < ROWS_PER_BLK / 2; i += 4) {
        float4 a0 = __ldcs(&base[(long long)(i + 0) * 2 * D4]);
        float4 a1 = __ldcs(&base[(long long)(i + 1) * 2 * D4]);
        float4 a2 = __ldcs(&base[(long long)(i + 2) * 2 * D4]);
        float4 a3 = __ldcs(&base[(long long)(i + 3) * 2 * D4]);
        acc += a0.x * m.x + a0.y * m.y + a0.z * m.z + a0.w * m.w;
        acc += a1.x * m.x + a1.y * m.y + a1.z * m.z + a1.w * m.w;
        acc += a2.x * m.x + a2.y * m.y + a2.z * m.z + a2.w * m.w;
        acc += a3.x * m.x + a3.y * m.y + a3.z * m.z + a3.w * m.w;
    }

    // block reduction
    #pragma unroll
    for (int o = 16; o > 0; o >>= 1) acc += __shfl_down_sync(0xffffffffu, acc, o);
    __shared__ float warpsum[8];
    if (lane == 0) warpsum[wid] = acc;
    __syncthreads();

    __shared__ bool s_last;
    if (tid == 0) {
        float v = 0.f;
        #pragma unroll
        for (int w = 0; w < 8; w++) v += warpsum[w];
        g_part[blockIdx.y * gridDim.x + blockIdx.x] = v;
        __threadfence();
        unsigned old = atomicAdd(&g_cnt, 1u);
        s_last = (old == NBLK - 1u);
    }
    __syncthreads();
    if (!s_last) return;

    // ================= fused finalization (last block only) =================
    __shared__ float  s_rowsum[MAX_REG];
    __shared__ double wsum[8];
    __shared__ float  wcnt[8];

    for (int r = wid; r < n_regimes && r < MAX_REG; r += 8) {
        const float* mr = mask + (long long)r * D;
        float s = 0.f;
        #pragma unroll
        for (int j = 0; j < D / 32; j++) s += __ldcg(mr + j * 32 + lane);
        #pragma unroll
        for (int o = 16; o > 0; o >>= 1) s += __shfl_down_sync(0xffffffffu, s, o);
        if (lane == 0) s_rowsum[r] = s;
    }
    __syncthreads();

    double lsum = 0.0;
    #pragma unroll 4
    for (int i = tid; i < NBLK; i += 256) lsum += (double)__ldcg(&g_part[i]);

    float c = 0.f;
    for (int bb = tid; bb < B && bb < MAX_B; bb += 256) {
        int ee = __ldcg(&regimes[bb]);
        if (ee < n_regimes) c += s_rowsum[(ee < 0 ? 0 : ee)];
    }

    #pragma unroll
    for (int o = 16; o > 0; o >>= 1) {
        lsum += __shfl_down_sync(0xffffffffu, lsum, o);
        c    += __shfl_down_sync(0xffffffffu, c, o);
    }
    if (lane == 0) { wsum[wid] = lsum; wcnt[wid] = c; }
    __syncthreads();
    if (tid == 0) {
        double loss = 0.0; float count = 0.f;
        #pragma unroll
        for (int w = 0; w < 8; w++) { loss += wsum[w]; count += wcnt[w]; }
        float lf = (float)loss;
        out[0] = (count > 0.f) ? (lf / count) : lf;   // INTERVENTION_STRENGTH = 1.0
        g_cnt = 0;                                    // reset for next graph replay
    }
}

extern "C" void kernel_launch(void* const* d_in, const int* in_sizes, int n_in,
                              void* d_out, int out_size) {
    const float* A    = (const float*)d_in[0];
    const float* mask = (const float*)d_in[1];
    const int*   reg  = (const int*)d_in[2];

    const int B = in_sizes[2];                 // 256
    const int n_regimes = in_sizes[1] / D;     // 16

    dim3 grid(D / ROWS_PER_BLK, B);            // (4, 256) = 1024 blocks, single wave
    k_reduce<<<grid, 256>>>(A, mask, reg, B, n_regimes, (float*)d_out);
}

// round 8
// speedup vs baseline: 1.0014x; 1.0014x over previous
#include <cuda_runtime.h>

// A [B=256, d=512, d=512] fp32, mask [16, 512] fp32, regimes [B] int32.
// Output: 1 float scalar.
#define D 512
#define D4 (D / 4)            // 128 float4 groups per row
#define ROWS_PER_ITEM 32
#define CHUNKS_PER_B (D / ROWS_PER_ITEM)   // 16
#define GRID_BLKS 1184        // 148 SMs * 8 resident target
#define MAX_REG 64
#define MAX_B 4096

__device__ float    g_part[GRID_BLKS];
__device__ unsigned g_work;   // work ticket; reset by finalize block
__device__ unsigned g_cnt;    // arrival counter; reset by finalize block

__global__ void __launch_bounds__(256, 6)
k_reduce(const float* __restrict__ A,
         const float* __restrict__ mask,
         const int* __restrict__ regimes,
         int B, int n_regimes, float* __restrict__ out) {
    const int tid  = threadIdx.x;
    const int wid  = tid >> 5;
    const int lane = tid & 31;
    const int j4   = tid & (D4 - 1);   // column float4 group
    const int rsub = tid >> 7;         // 0/1 row interleave
    const int n_items = B * CHUNKS_PER_B;

    __shared__ unsigned s_idx;
    float acc = 0.f;

    for (;;) {
        if (tid == 0) s_idx = atomicAdd(&g_work, 1u);
        __syncthreads();
        const unsigned idx = s_idx;
        __syncthreads();            // protect s_idx before next iteration's write
        if (idx >= (unsigned)n_items) break;

        const int b = idx >> 4;                  // idx / CHUNKS_PER_B
        const int c = idx & (CHUNKS_PER_B - 1);

        const int e = regimes[b];
        float4 m = make_float4(0.f, 0.f, 0.f, 0.f);
        if (e < n_regimes) {
            const int ec = e < 0 ? 0 : e;
            m = __ldg(reinterpret_cast<const float4*>(mask + (long long)ec * D) + j4);
        }

        const float4* base = reinterpret_cast<const float4*>(
            A + ((long long)b * D + (long long)c * ROWS_PER_ITEM + rsub) * D) + j4;

        #pragma unroll
        for (int i = 0; i < ROWS_PER_ITEM / 2; i += 4) {
            float4 a0 = __ldcs(&base[(long long)(i + 0) * 2 * D4]);
            float4 a1 = __ldcs(&base[(long long)(i + 1) * 2 * D4]);
            float4 a2 = __ldcs(&base[(long long)(i + 2) * 2 * D4]);
            float4 a3 = __ldcs(&base[(long long)(i + 3) * 2 * D4]);
            acc += a0.x * m.x + a0.y * m.y + a0.z * m.z + a0.w * m.w;
            acc += a1.x * m.x + a1.y * m.y + a1.z * m.z + a1.w * m.w;
            acc += a2.x * m.x + a2.y * m.y + a2.z * m.z + a2.w * m.w;
            acc += a3.x * m.x + a3.y * m.y + a3.z * m.z + a3.w * m.w;
        }
    }

    // block reduction of the accumulated partial
    #pragma unroll
    for (int o = 16; o > 0; o >>= 1) acc += __shfl_down_sync(0xffffffffu, acc, o);
    __shared__ float warpsum[8];
    if (lane == 0) warpsum[wid] = acc;
    __syncthreads();

    __shared__ bool s_last;
    if (tid == 0) {
        float v = 0.f;
        #pragma unroll
        for (int w = 0; w < 8; w++) v += warpsum[w];
        g_part[blockIdx.x] = v;
        __threadfence();
        unsigned old = atomicAdd(&g_cnt, 1u);
        s_last = (old == (unsigned)gridDim.x - 1u);
    }
    __syncthreads();
    if (!s_last) return;

    // ================= fused finalization (last block only) =================
    __shared__ float  s_rowsum[MAX_REG];
    __shared__ double wsum[8];
    __shared__ float  wcnt[8];

    for (int r = wid; r < n_regimes && r < MAX_REG; r += 8) {
        const float* mr = mask + (long long)r * D;
        float s = 0.f;
        #pragma unroll
        for (int j = 0; j < D / 32; j++) s += __ldcg(mr + j * 32 + lane);
        #pragma unroll
        for (int o = 16; o > 0; o >>= 1) s += __shfl_down_sync(0xffffffffu, s, o);
        if (lane == 0) s_rowsum[r] = s;
    }
    __syncthreads();

    double lsum = 0.0;
    #pragma unroll 4
    for (int i = tid; i < GRID_BLKS; i += 256) lsum += (double)__ldcg(&g_part[i]);

    float c = 0.f;
    for (int bb = tid; bb < B && bb < MAX_B; bb += 256) {
        int ee = __ldcg(&regimes[bb]);
        if (ee < n_regimes) c += s_rowsum[(ee < 0 ? 0 : ee)];
    }

    #pragma unroll
    for (int o = 16; o > 0; o >>= 1) {
        lsum += __shfl_down_sync(0xffffffffu, lsum, o);
        c    += __shfl_down_sync(0xffffffffu, c, o);
    }
    if (lane == 0) { wsum[wid] = lsum; wcnt[wid] = c; }
    __syncthreads();
    if (tid == 0) {
        double loss = 0.0; float count = 0.f;
        #pragma unroll
        for (int w = 0; w < 8; w++) { loss += wsum[w]; count += wcnt[w]; }
        float lf = (float)loss;
        out[0] = (count > 0.f) ? (lf / count) : lf;   // INTERVENTION_STRENGTH = 1.0
        g_work = 0;                                   // reset for next graph replay
        g_cnt  = 0;
    }
}

extern "C" void kernel_launch(void* const* d_in, const int* in_sizes, int n_in,
                              void* d_out, int out_size) {
    const float* A    = (const float*)d_in[0];
    const float* mask = (const float*)d_in[1];
    const int*   reg  = (const int*)d_in[2];

    const int B = in_sizes[2];                 // 256
    const int n_regimes = in_sizes[1] / D;     // 16

    k_reduce<<<GRID_BLKS, 256>>>(A, mask, reg, B, n_regimes, (float*)d_out);
}